// round 5
// baseline (speedup 1.0000x reference)
#include <cuda_runtime.h>
#include <cstdint>

// Problem constants
#define BB 16
#define SS 4096
#define EE 1024
#define HH 512

// Scratch (device globals — no allocation allowed)
__device__ float g_db[BB * HH];       // dec_proj + bd + be
__device__ float g_scores[BB * SS];
__device__ float g_attn[BB * SS];
__device__ float g_WeT[HH * EE];      // We in fragment-major tf32-rounded layout (see k0_pack)

// ---------------- helpers ----------------
__device__ __forceinline__ uint32_t f2tf(float x) {
    uint32_t u;
    asm("cvt.rna.tf32.f32 %0, %1;" : "=r"(u) : "f"(x));
    return u;
}
__device__ __forceinline__ void mma_tf32(float c[4],
                                         uint32_t a0, uint32_t a1, uint32_t a2, uint32_t a3,
                                         uint32_t b0, uint32_t b1) {
    asm volatile(
        "mma.sync.aligned.m16n8k8.row.col.f32.tf32.tf32.f32 "
        "{%0,%1,%2,%3}, {%4,%5,%6,%7}, {%8,%9}, {%0,%1,%2,%3};\n"
        : "+f"(c[0]), "+f"(c[1]), "+f"(c[2]), "+f"(c[3])
        : "r"(a0), "r"(a1), "r"(a2), "r"(a3), "r"(b0), "r"(b1));
}
__device__ __forceinline__ void cp16(float* dst_smem, const float* src) {
    uint32_t d = (uint32_t)__cvta_generic_to_shared(dst_smem);
    asm volatile("cp.async.cg.shared.global [%0], [%1], 16;\n" :: "r"(d), "l"(src));
}
__device__ __forceinline__ float tanh_acc(float x) {
    float xa = fminf(fmaxf(x, -12.f), 12.f);
    float e = __expf(2.f * xa);
    return (e - 1.f) / (e + 1.f);
}

// ---------------- K0: pack We -> g_WeT (fragment-major, tf32-rounded) ----------------
// Layout (word index): [kc:32][w:16][chunk:8][lane:32][j:4]
//   chunk = ks*2+np (ks: k-octet 0..3, np: nt-pair 0..1)
//   j: nt = np*2 + (j>>1), b01 = j&1
//   value = rna_tf32( We[e][h] ),  e = kc*32 + ks*8 + t4 + b01*4,  h = w*32 + nt*8 + g
// This makes the SMEM stage a pure linear copy, and each thread's B fragment one LDS.128.
__global__ void k0_pack(const float* __restrict__ We) {
    int idx = blockIdx.x * 256 + threadIdx.x;          // 524288 total
    int kc   = idx >> 14;
    int rem  = idx & 16383;
    int w    = rem >> 10;
    int r2   = rem & 1023;
    int chunk = r2 >> 7;
    int ks = chunk >> 1, np = chunk & 1;
    int lane = (r2 >> 2) & 31;
    int j    = r2 & 3;
    int g = lane >> 2, t4 = lane & 3;
    int nt = np * 2 + (j >> 1), b01 = j & 1;
    int h = w * 32 + nt * 8 + g;
    int e = kc * 32 + ks * 8 + t4 + b01 * 4;
    g_WeT[idx] = __uint_as_float(f2tf(We[e * HH + h]));
}

// ---------------- K1: decoder projection + biases ----------------
__global__ void k1_decproj(const float* __restrict__ dec, const float* __restrict__ Wd,
                           const float* __restrict__ bd, const float* __restrict__ be) {
    int b = blockIdx.x;          // 16 blocks
    int h = threadIdx.x;         // 512 threads
    const float* d = dec + b * EE;
    float s0 = 0.f, s1 = 0.f, s2 = 0.f, s3 = 0.f;
    for (int e = 0; e < EE; e += 4) {
        s0 += d[e + 0] * Wd[(e + 0) * HH + h];
        s1 += d[e + 1] * Wd[(e + 1) * HH + h];
        s2 += d[e + 2] * Wd[(e + 2) * HH + h];
        s3 += d[e + 3] * Wd[(e + 3) * HH + h];
    }
    g_db[b * HH + h] = (s0 + s1) + (s2 + s3) + bd[h] + be[h];
}

// ---------------- K2: mma.sync tf32, fragment-major SMEM, fused epilogue ----------------
// 512 threads (16 warps). Tile M=128 s-rows x N=512 h (32/warp), K streamed in 32-chunks.
// SMEM words: A0@0 A1@4096 (128x32 frag-major), B0@8192 B1@24576 (512x32 frag-major),
//             db@40960, wo@41472, red@41984 (16x128). Total 44032 words = 176128 B.
#define A_W(buf) ((buf) * 4096)
#define B_W(buf) (8192 + (buf) * 16384)
#define DB_W 40960
#define WO_W 41472
#define RED_W 41984
#define SMEM_K2 (44032 * 4)

__global__ __launch_bounds__(512, 1)
void k2_scores(const float* __restrict__ enc, const float* __restrict__ Wo,
               const float* __restrict__ bo) {
    extern __shared__ float sm[];
    const int tid = threadIdx.x, w = tid >> 5, lane = tid & 31;
    const int t4 = lane & 3;
    const int b = blockIdx.y, s0 = blockIdx.x * 128;
    const float* A = enc + (size_t)(b * SS + s0) * EE;

    for (int i = tid; i < HH; i += 512) {
        sm[DB_W + i] = g_db[b * HH + i];
        sm[WO_W + i] = Wo[i];
    }

    // Per-thread A writer mapping: thread writes float4s p = tid, tid+512 of the
    // 128x32 stage. p -> (row r, col-quad c). Fragment-major dest:
    // word = (ks*8+mt)*128 + gg*16 + q*4 + hi + 2*half   (q = element 0..3)
    size_t aoff[2];
    int    wab[2];
#pragma unroll
    for (int jj = 0; jj < 2; jj++) {
        int p = tid + jj * 512;
        int r = p >> 3, c = p & 7;
        int gg = r & 7, mt = r >> 4, hi = (r >> 3) & 1;
        int ks = c >> 1, half = c & 1;
        aoff[jj] = (size_t)r * EE + c * 4;
        wab[jj]  = (ks * 8 + mt) * 128 + gg * 16 + hi + 2 * half;
    }

    // Prologue: A stages 0,1 (LDG + rounded STS), B stages 0,1 (cp.async)
#pragma unroll
    for (int st = 0; st < 2; st++) {
#pragma unroll
        for (int jj = 0; jj < 2; jj++) {
            float4 v = *(const float4*)(A + aoff[jj] + st * 32);
            float* d = sm + A_W(st) + wab[jj];
            d[0]  = __uint_as_float(f2tf(v.x));
            d[4]  = __uint_as_float(f2tf(v.y));
            d[8]  = __uint_as_float(f2tf(v.z));
            d[12] = __uint_as_float(f2tf(v.w));
        }
#pragma unroll
        for (int m = 0; m < 8; m++) {
            int i16 = tid + m * 512;
            cp16(sm + B_W(st) + i16 * 4, g_WeT + (size_t)st * 16384 + i16 * 4);
        }
        asm volatile("cp.async.commit_group;\n");
    }

    float acc[8][4][4] = {};      // [mt][nt][elem]

    for (int kc = 0; kc < 32; kc++) {
        // Prefetch A(kc+2) into regs before compute (LDG latency hidden by MMA)
        float4 pf0, pf1;
        if (kc + 2 < 32) {
            pf0 = *(const float4*)(A + aoff[0] + (kc + 2) * 32);
            pf1 = *(const float4*)(A + aoff[1] + (kc + 2) * 32);
        }
        asm volatile("cp.async.wait_group 1;\n");
        __syncthreads();

        const float* Ab = sm + A_W(kc & 1);
        const float* Bb = sm + B_W(kc & 1) + w * 1024;
#pragma unroll
        for (int ks = 0; ks < 4; ks++) {
            uint4 af[8];
#pragma unroll
            for (int mt = 0; mt < 8; mt++)
                af[mt] = *(const uint4*)(Ab + (ks * 8 + mt) * 128 + lane * 4);
            uint4 bf0 = *(const uint4*)(Bb + (ks * 2 + 0) * 128 + lane * 4);
            uint4 bf1 = *(const uint4*)(Bb + (ks * 2 + 1) * 128 + lane * 4);
#pragma unroll
            for (int mt = 0; mt < 8; mt++) {
                mma_tf32(acc[mt][0], af[mt].x, af[mt].y, af[mt].z, af[mt].w, bf0.x, bf0.y);
                mma_tf32(acc[mt][1], af[mt].x, af[mt].y, af[mt].z, af[mt].w, bf0.z, bf0.w);
                mma_tf32(acc[mt][2], af[mt].x, af[mt].y, af[mt].z, af[mt].w, bf1.x, bf1.y);
                mma_tf32(acc[mt][3], af[mt].x, af[mt].y, af[mt].z, af[mt].w, bf1.z, bf1.w);
            }
        }
        __syncthreads();

        if (kc + 2 < 32) {
            int buf = kc & 1;
            float* d0 = sm + A_W(buf) + wab[0];
            d0[0]  = __uint_as_float(f2tf(pf0.x));
            d0[4]  = __uint_as_float(f2tf(pf0.y));
            d0[8]  = __uint_as_float(f2tf(pf0.z));
            d0[12] = __uint_as_float(f2tf(pf0.w));
            float* d1 = sm + A_W(buf) + wab[1];
            d1[0]  = __uint_as_float(f2tf(pf1.x));
            d1[4]  = __uint_as_float(f2tf(pf1.y));
            d1[8]  = __uint_as_float(f2tf(pf1.z));
            d1[12] = __uint_as_float(f2tf(pf1.w));
#pragma unroll
            for (int m = 0; m < 8; m++) {
                int i16 = tid + m * 512;
                cp16(sm + B_W(buf) + i16 * 4, g_WeT + (size_t)(kc + 2) * 16384 + i16 * 4);
            }
        }
        asm volatile("cp.async.commit_group;\n");
    }

    // Epilogue: tanh(acc + db) * Wo, reduce over h
    // C frag (m16n8): c0=(g, 2*t4), c1=(g, 2*t4+1), c2=(g+8, 2*t4), c3=(g+8, 2*t4+1)
    float ps[16] = {};
#pragma unroll
    for (int mt = 0; mt < 8; mt++) {
#pragma unroll
        for (int nt = 0; nt < 4; nt++) {
            int col = w * 32 + nt * 8 + t4 * 2;
            float d0 = sm[DB_W + col], d1 = sm[DB_W + col + 1];
            float w0 = sm[WO_W + col], w1 = sm[WO_W + col + 1];
            ps[mt * 2]     += tanh_acc(acc[mt][nt][0] + d0) * w0
                            + tanh_acc(acc[mt][nt][1] + d1) * w1;
            ps[mt * 2 + 1] += tanh_acc(acc[mt][nt][2] + d0) * w0
                            + tanh_acc(acc[mt][nt][3] + d1) * w1;
        }
    }
#pragma unroll
    for (int i = 0; i < 16; i++) {
        ps[i] += __shfl_xor_sync(0xffffffffu, ps[i], 1);
        ps[i] += __shfl_xor_sync(0xffffffffu, ps[i], 2);
    }
    if (t4 == 0) {
        int g = lane >> 2;
#pragma unroll
        for (int mt = 0; mt < 8; mt++) {
            sm[RED_W + w * 128 + mt * 16 + g]     = ps[mt * 2];
            sm[RED_W + w * 128 + mt * 16 + 8 + g] = ps[mt * 2 + 1];
        }
    }
    __syncthreads();
    if (tid < 128) {
        float sc = bo[0];
#pragma unroll
        for (int ww = 0; ww < 16; ww++) sc += sm[RED_W + ww * 128 + tid];
        g_scores[b * SS + s0 + tid] = sc;
    }
}

// ---------------- K3: softmax over S per batch ----------------
__global__ void k3_softmax() {
    int b = blockIdx.x, tid = threadIdx.x;      // 256 threads
    __shared__ float sred[256];
    const float* sc = g_scores + b * SS;
    float mx = -1e30f;
    for (int i = tid; i < SS; i += 256) mx = fmaxf(mx, sc[i]);
    sred[tid] = mx; __syncthreads();
    for (int st = 128; st > 0; st >>= 1) {
        if (tid < st) sred[tid] = fmaxf(sred[tid], sred[tid + st]);
        __syncthreads();
    }
    mx = sred[0]; __syncthreads();
    float sum = 0.f;
    for (int i = tid; i < SS; i += 256) {
        float e = __expf(sc[i] - mx);
        g_attn[b * SS + i] = e;
        sum += e;
    }
    sred[tid] = sum; __syncthreads();
    for (int st = 128; st > 0; st >>= 1) {
        if (tid < st) sred[tid] += sred[tid + st];
        __syncthreads();
    }
    float inv = 1.f / sred[0];
    for (int i = tid; i < SS; i += 256) g_attn[b * SS + i] *= inv;
}

// ---------------- K4: context = attn . enc ----------------
__global__ __launch_bounds__(128)
void k4_context(const float* __restrict__ enc, float* __restrict__ out) {
    int b  = blockIdx.z;
    int e  = blockIdx.x * 128 + threadIdx.x;
    int s0 = blockIdx.y * 128;                  // 128 rows per block -> 4096 blocks
    __shared__ float at[128];
    at[threadIdx.x] = g_attn[b * SS + s0 + threadIdx.x];
    __syncthreads();
    const float* ep = enc + (size_t)(b * SS + s0) * EE + e;
    float a0 = 0.f, a1 = 0.f, a2 = 0.f, a3 = 0.f;
    float a4 = 0.f, a5 = 0.f, a6 = 0.f, a7 = 0.f;
#pragma unroll 2
    for (int s = 0; s < 128; s += 8) {
        a0 += at[s + 0] * ep[(size_t)(s + 0) * EE];
        a1 += at[s + 1] * ep[(size_t)(s + 1) * EE];
        a2 += at[s + 2] * ep[(size_t)(s + 2) * EE];
        a3 += at[s + 3] * ep[(size_t)(s + 3) * EE];
        a4 += at[s + 4] * ep[(size_t)(s + 4) * EE];
        a5 += at[s + 5] * ep[(size_t)(s + 5) * EE];
        a6 += at[s + 6] * ep[(size_t)(s + 6) * EE];
        a7 += at[s + 7] * ep[(size_t)(s + 7) * EE];
    }
    atomicAdd(&out[b * EE + e], ((a0 + a1) + (a2 + a3)) + ((a4 + a5) + (a6 + a7)));
}

// ---------------- launch ----------------
extern "C" void kernel_launch(void* const* d_in, const int* in_sizes, int n_in,
                              void* d_out, int out_size) {
    const float* enc = (const float*)d_in[0];
    const float* dec = (const float*)d_in[1];
    const float* We  = (const float*)d_in[2];
    const float* be  = (const float*)d_in[3];
    const float* Wd  = (const float*)d_in[4];
    const float* bd  = (const float*)d_in[5];
    const float* Wo  = (const float*)d_in[6];
    const float* bo  = (const float*)d_in[7];
    float* out = (float*)d_out;

    k0_pack<<<(HH * EE) / 256, 256>>>(We);
    k1_decproj<<<BB, HH>>>(dec, Wd, bd, be);

    cudaFuncSetAttribute(k2_scores, cudaFuncAttributeMaxDynamicSharedMemorySize, SMEM_K2);
    k2_scores<<<dim3(SS / 128, BB), 512, SMEM_K2>>>(enc, Wo, bo);

    k3_softmax<<<BB, 256>>>();

    cudaMemsetAsync(d_out, 0, (size_t)BB * EE * sizeof(float));
    k4_context<<<dim3(EE / 128, SS / 128, BB), 128>>>(enc, out);
}

// round 6
// speedup vs baseline: 2.1603x; 2.1603x over previous
#include <cuda_runtime.h>
#include <cstdint>

// Problem constants
#define BB 16
#define SS 4096
#define EE 1024
#define HH 512

// Scratch (device globals — no allocation allowed)
__device__ float g_db[BB * HH];       // dec_proj + bd + be
__device__ float g_scores[BB * SS];
__device__ float g_attn[BB * SS];
__device__ float g_WeT[HH * EE];      // We in fragment-major tf32-rounded layout (see k0_pack)

// ---------------- helpers ----------------
__device__ __forceinline__ uint32_t f2tf(float x) {
    uint32_t u;
    asm("cvt.rna.tf32.f32 %0, %1;" : "=r"(u) : "f"(x));
    return u;
}
__device__ __forceinline__ void mma_tf32(float c[4],
                                         uint32_t a0, uint32_t a1, uint32_t a2, uint32_t a3,
                                         uint32_t b0, uint32_t b1) {
    asm volatile(
        "mma.sync.aligned.m16n8k8.row.col.f32.tf32.tf32.f32 "
        "{%0,%1,%2,%3}, {%4,%5,%6,%7}, {%8,%9}, {%0,%1,%2,%3};\n"
        : "+f"(c[0]), "+f"(c[1]), "+f"(c[2]), "+f"(c[3])
        : "r"(a0), "r"(a1), "r"(a2), "r"(a3), "r"(b0), "r"(b1));
}
__device__ __forceinline__ void cp16(float* dst_smem, const float* src) {
    uint32_t d = (uint32_t)__cvta_generic_to_shared(dst_smem);
    asm volatile("cp.async.cg.shared.global [%0], [%1], 16;\n" :: "r"(d), "l"(src));
}
__device__ __forceinline__ float tanh_acc(float x) {
    float xa = fminf(fmaxf(x, -12.f), 12.f);
    float e = __expf(2.f * xa);
    return (e - 1.f) / (e + 1.f);
}

// ---------------- K0: pack We -> g_WeT (fragment-major for 8-warp k2) ----------------
// word idx = kc*16384 + w*2048 + chunk*128 + lane*4 + j
//   chunk = ks*4 + np (ks: k-octet 0..3, np: nt-pair 0..3)
//   nt = np*2 + (j>>1), b01 = j&1, g = lane>>2, t4 = lane&3
//   value = rna_tf32( We[e][h] ), e = kc*32 + ks*8 + t4 + b01*4, h = w*64 + nt*8 + g
__global__ void k0_pack(const float* __restrict__ We) {
    int idx = blockIdx.x * 256 + threadIdx.x;          // 524288 total
    int kc   = idx >> 14;
    int rem  = idx & 16383;
    int w    = rem >> 11;
    int r2   = rem & 2047;
    int chunk = r2 >> 7;
    int ks = chunk >> 2, np = chunk & 3;
    int lane = (r2 >> 2) & 31;
    int j    = r2 & 3;
    int g = lane >> 2, t4 = lane & 3;
    int nt = np * 2 + (j >> 1), b01 = j & 1;
    int h = w * 64 + nt * 8 + g;
    int e = kc * 32 + ks * 8 + t4 + b01 * 4;
    g_WeT[idx] = __uint_as_float(f2tf(We[e * HH + h]));
}

// ---------------- K1: decoder projection + biases ----------------
__global__ void k1_decproj(const float* __restrict__ dec, const float* __restrict__ Wd,
                           const float* __restrict__ bd, const float* __restrict__ be) {
    int b = blockIdx.x;                                 // (16, 4) grid, 128 threads
    int h = blockIdx.y * 128 + threadIdx.x;
    const float* d = dec + b * EE;
    float s0 = 0.f, s1 = 0.f, s2 = 0.f, s3 = 0.f;
    for (int e = 0; e < EE; e += 4) {
        s0 += d[e + 0] * Wd[(e + 0) * HH + h];
        s1 += d[e + 1] * Wd[(e + 1) * HH + h];
        s2 += d[e + 2] * Wd[(e + 2) * HH + h];
        s3 += d[e + 3] * Wd[(e + 3) * HH + h];
    }
    g_db[b * HH + h] = (s0 + s1) + (s2 + s3) + bd[h] + be[h];
}

// ---------------- K2: mma.sync tf32, fragment-major, 256 thr, M=64 tile ----------------
// 8 warps; warp w owns h-cols [w*64, w*64+64). acc[4][8][4] = 128 regs/thread.
// SMEM words: A0@0 A1@2048 (16 chunks x 128), B0@4096 B1@20480 (128 chunks x 128),
//             db@36864, wo@37376, red@37888 (8x64). Total 38400 words = 153600 B.
#define A_W(buf) ((buf) * 2048)
#define B_W(buf) (4096 + (buf) * 16384)
#define DB_W 36864
#define WO_W 37376
#define RED_W 37888
#define SMEM_K2 (38400 * 4)

__global__ __launch_bounds__(256, 1)
void k2_scores(const float* __restrict__ enc, const float* __restrict__ Wo,
               const float* __restrict__ bo) {
    extern __shared__ float sm[];
    const int tid = threadIdx.x, w = tid >> 5, lane = tid & 31;
    const int g = lane >> 2, t4 = lane & 3;
    const int b = blockIdx.y, s0 = blockIdx.x * 64;
    const float* A = enc + (size_t)(b * SS + s0) * EE;

    for (int i = tid; i < HH; i += 256) {
        sm[DB_W + i] = g_db[b * HH + i];
        sm[WO_W + i] = Wo[i];
    }

    // A writer: thread handles fragment chunks c16 = (tid>>5) and (tid>>5)+8 at its lane.
    // Each chunk-write = gather 4 scalar LDGs -> 1 conflict-free STS.128 (fragment-major).
    size_t ga[2][2];    // [jj][row-half]; cols +0 / +4 derived
    int    wa[2];
#pragma unroll
    for (int jj = 0; jj < 2; jj++) {
        int c16 = (tid >> 5) + jj * 8;
        int ks = c16 >> 2, mt = c16 & 3;
        ga[jj][0] = (size_t)(mt * 16 + g) * EE + ks * 8 + t4;
        ga[jj][1] = (size_t)(mt * 16 + 8 + g) * EE + ks * 8 + t4;
        wa[jj] = c16 * 128 + lane * 4;
    }

    auto storeA = [&](int buf, int jj, float v0, float v1, float v2, float v3) {
        uint4 u;
        u.x = f2tf(v0); u.y = f2tf(v1); u.z = f2tf(v2); u.w = f2tf(v3);
        *(uint4*)(sm + A_W(buf) + wa[jj]) = u;
    };
    auto loadA = [&](int kc, int buf) {
#pragma unroll
        for (int jj = 0; jj < 2; jj++) {
            float v0 = A[ga[jj][0] + kc * 32];
            float v1 = A[ga[jj][1] + kc * 32];
            float v2 = A[ga[jj][0] + kc * 32 + 4];
            float v3 = A[ga[jj][1] + kc * 32 + 4];
            storeA(buf, jj, v0, v1, v2, v3);
        }
    };
    auto loadB = [&](int kc, int buf) {
#pragma unroll
        for (int m = 0; m < 16; m++) {
            int i16 = tid + m * 256;
            cp16(sm + B_W(buf) + i16 * 4, g_WeT + (size_t)kc * 16384 + i16 * 4);
        }
    };

    loadA(0, 0); loadB(0, 0);
    asm volatile("cp.async.commit_group;\n");
    loadA(1, 1); loadB(1, 1);
    asm volatile("cp.async.commit_group;\n");

    float acc[4][8][4] = {};      // [mt][nt][elem]

    for (int kc = 0; kc < 32; kc++) {
        // Prefetch A(kc+2) into regs (LDG latency hidden under MMA)
        float p00, p01, p02, p03, p10, p11, p12, p13;
        if (kc + 2 < 32) {
            p00 = A[ga[0][0] + (kc + 2) * 32]; p01 = A[ga[0][1] + (kc + 2) * 32];
            p02 = A[ga[0][0] + (kc + 2) * 32 + 4]; p03 = A[ga[0][1] + (kc + 2) * 32 + 4];
            p10 = A[ga[1][0] + (kc + 2) * 32]; p11 = A[ga[1][1] + (kc + 2) * 32];
            p12 = A[ga[1][0] + (kc + 2) * 32 + 4]; p13 = A[ga[1][1] + (kc + 2) * 32 + 4];
        }
        asm volatile("cp.async.wait_group 1;\n");
        __syncthreads();

        const float* Ab = sm + A_W(kc & 1);
        const float* Bb = sm + B_W(kc & 1) + w * 2048;
#pragma unroll
        for (int ks = 0; ks < 4; ks++) {
            uint4 af[4];
#pragma unroll
            for (int mt = 0; mt < 4; mt++)
                af[mt] = *(const uint4*)(Ab + (ks * 4 + mt) * 128 + lane * 4);
#pragma unroll
            for (int np = 0; np < 4; np++) {
                uint4 bf = *(const uint4*)(Bb + (ks * 4 + np) * 128 + lane * 4);
#pragma unroll
                for (int mt = 0; mt < 4; mt++) {
                    mma_tf32(acc[mt][np * 2],     af[mt].x, af[mt].y, af[mt].z, af[mt].w, bf.x, bf.y);
                    mma_tf32(acc[mt][np * 2 + 1], af[mt].x, af[mt].y, af[mt].z, af[mt].w, bf.z, bf.w);
                }
            }
        }
        __syncthreads();

        if (kc + 2 < 32) {
            int buf = kc & 1;
            storeA(buf, 0, p00, p01, p02, p03);
            storeA(buf, 1, p10, p11, p12, p13);
            loadB(kc + 2, buf);
        }
        asm volatile("cp.async.commit_group;\n");
    }

    // Epilogue: tanh(acc + db) * Wo, reduce over h (validated in R2)
    float ps[8] = {};
#pragma unroll
    for (int mt = 0; mt < 4; mt++) {
#pragma unroll
        for (int nt = 0; nt < 8; nt++) {
            int col = w * 64 + nt * 8 + t4 * 2;
            float d0 = sm[DB_W + col], d1 = sm[DB_W + col + 1];
            float w0 = sm[WO_W + col], w1 = sm[WO_W + col + 1];
            ps[mt * 2]     += tanh_acc(acc[mt][nt][0] + d0) * w0
                            + tanh_acc(acc[mt][nt][1] + d1) * w1;
            ps[mt * 2 + 1] += tanh_acc(acc[mt][nt][2] + d0) * w0
                            + tanh_acc(acc[mt][nt][3] + d1) * w1;
        }
    }
#pragma unroll
    for (int i = 0; i < 8; i++) {
        ps[i] += __shfl_xor_sync(0xffffffffu, ps[i], 1);
        ps[i] += __shfl_xor_sync(0xffffffffu, ps[i], 2);
    }
    if (t4 == 0) {
#pragma unroll
        for (int mt = 0; mt < 4; mt++) {
            sm[RED_W + w * 64 + mt * 16 + g]     = ps[mt * 2];
            sm[RED_W + w * 64 + mt * 16 + 8 + g] = ps[mt * 2 + 1];
        }
    }
    __syncthreads();
    if (tid < 64) {
        float sc = bo[0];
#pragma unroll
        for (int ww = 0; ww < 8; ww++) sc += sm[RED_W + ww * 64 + tid];
        g_scores[b * SS + s0 + tid] = sc;
    }
}

// ---------------- K3: softmax over S per batch ----------------
__global__ void k3_softmax() {
    int b = blockIdx.x, tid = threadIdx.x;      // 1024 threads
    __shared__ float sred[1024];
    const float* sc = g_scores + b * SS;
    float mx = -1e30f;
    for (int i = tid; i < SS; i += 1024) mx = fmaxf(mx, sc[i]);
    sred[tid] = mx; __syncthreads();
    for (int st = 512; st > 0; st >>= 1) {
        if (tid < st) sred[tid] = fmaxf(sred[tid], sred[tid + st]);
        __syncthreads();
    }
    mx = sred[0]; __syncthreads();
    float sum = 0.f;
    for (int i = tid; i < SS; i += 1024) {
        float e = __expf(sc[i] - mx);
        g_attn[b * SS + i] = e;
        sum += e;
    }
    sred[tid] = sum; __syncthreads();
    for (int st = 512; st > 0; st >>= 1) {
        if (tid < st) sred[tid] += sred[tid + st];
        __syncthreads();
    }
    float inv = 1.f / sred[0];
    for (int i = tid; i < SS; i += 1024) g_attn[b * SS + i] *= inv;
}

// ---------------- K4: context = attn . enc (float4, unroll 8) ----------------
__global__ __launch_bounds__(128)
void k4_context(const float* __restrict__ enc, float* __restrict__ out) {
    int b  = blockIdx.z;
    int e4 = (blockIdx.x * 128 + threadIdx.x) * 4;   // 2 blocks cover EE=1024
    int s0 = blockIdx.y * 128;
    __shared__ float at[128];
    at[threadIdx.x] = g_attn[b * SS + s0 + threadIdx.x];
    __syncthreads();
    const float* ep = enc + (size_t)(b * SS + s0) * EE + e4;
    float x0 = 0.f, y0 = 0.f, z0 = 0.f, w0 = 0.f;
    float x1 = 0.f, y1 = 0.f, z1 = 0.f, w1 = 0.f;
#pragma unroll 2
    for (int s = 0; s < 128; s += 8) {
        float4 v0 = *(const float4*)(ep + (size_t)(s + 0) * EE);
        float4 v1 = *(const float4*)(ep + (size_t)(s + 1) * EE);
        float4 v2 = *(const float4*)(ep + (size_t)(s + 2) * EE);
        float4 v3 = *(const float4*)(ep + (size_t)(s + 3) * EE);
        float4 v4 = *(const float4*)(ep + (size_t)(s + 4) * EE);
        float4 v5 = *(const float4*)(ep + (size_t)(s + 5) * EE);
        float4 v6 = *(const float4*)(ep + (size_t)(s + 6) * EE);
        float4 v7 = *(const float4*)(ep + (size_t)(s + 7) * EE);
        float a0 = at[s], a1 = at[s + 1], a2 = at[s + 2], a3 = at[s + 3];
        float a4 = at[s + 4], a5 = at[s + 5], a6 = at[s + 6], a7 = at[s + 7];
        x0 += a0 * v0.x + a1 * v1.x + a2 * v2.x + a3 * v3.x;
        y0 += a0 * v0.y + a1 * v1.y + a2 * v2.y + a3 * v3.y;
        z0 += a0 * v0.z + a1 * v1.z + a2 * v2.z + a3 * v3.z;
        w0 += a0 * v0.w + a1 * v1.w + a2 * v2.w + a3 * v3.w;
        x1 += a4 * v4.x + a5 * v5.x + a6 * v6.x + a7 * v7.x;
        y1 += a4 * v4.y + a5 * v5.y + a6 * v6.y + a7 * v7.y;
        z1 += a4 * v4.z + a5 * v5.z + a6 * v6.z + a7 * v7.z;
        w1 += a4 * v4.w + a5 * v5.w + a6 * v6.w + a7 * v7.w;
    }
    atomicAdd(&out[b * EE + e4 + 0], x0 + x1);
    atomicAdd(&out[b * EE + e4 + 1], y0 + y1);
    atomicAdd(&out[b * EE + e4 + 2], z0 + z1);
    atomicAdd(&out[b * EE + e4 + 3], w0 + w1);
}

// ---------------- launch ----------------
extern "C" void kernel_launch(void* const* d_in, const int* in_sizes, int n_in,
                              void* d_out, int out_size) {
    const float* enc = (const float*)d_in[0];
    const float* dec = (const float*)d_in[1];
    const float* We  = (const float*)d_in[2];
    const float* be  = (const float*)d_in[3];
    const float* Wd  = (const float*)d_in[4];
    const float* bd  = (const float*)d_in[5];
    const float* Wo  = (const float*)d_in[6];
    const float* bo  = (const float*)d_in[7];
    float* out = (float*)d_out;

    k0_pack<<<(HH * EE) / 256, 256>>>(We);
    k1_decproj<<<dim3(BB, 4), 128>>>(dec, Wd, bd, be);

    cudaFuncSetAttribute(k2_scores, cudaFuncAttributeMaxDynamicSharedMemorySize, SMEM_K2);
    k2_scores<<<dim3(SS / 64, BB), 256, SMEM_K2>>>(enc, Wo, bo);

    k3_softmax<<<BB, 1024>>>();

    cudaMemsetAsync(d_out, 0, (size_t)BB * EE * sizeof(float));
    k4_context<<<dim3(EE / 512, SS / 128, BB), 128>>>(enc, out);
}